// round 12
// baseline (speedup 1.0000x reference)
#include <cuda_runtime.h>
#include <cuda_bf16.h>
#include <cstdint>

#define BB 2
#define SS 2048
#define DD 2048
#define HH 16
#define KVH 4
#define HD 128
#define II 8192
#define TT (BB*SS)   // 4096 tokens

// ---------------- scratch (static device memory; no allocations) ----------------
// xn(8.4M) q(8.4M) k(2.1M) v(2.1M) attn(8.4M) h2(8.4M) xn2(8.4M) gate(33.5M) up(33.5M)
#define OFF_XN   ((size_t)0)
#define OFF_Q    ((size_t)8388608)
#define OFF_K    ((size_t)16777216)
#define OFF_V    ((size_t)18874368)
#define OFF_ATTN ((size_t)20971520)
#define OFF_H2   ((size_t)29360128)
#define OFF_XN2  ((size_t)37748736)
#define OFF_GATE ((size_t)46137344)
#define OFF_UP   ((size_t)79691776)
#define SCRATCH_FLOATS ((size_t)113246208)
__device__ float g_scratch[SCRATCH_FLOATS];

// ---------------- packed f32x2 helpers (Blackwell) ----------------
__device__ __forceinline__ unsigned long long pack2(float lo, float hi) {
    unsigned long long r;
    asm("mov.b64 %0, {%1, %2};" : "=l"(r) : "f"(lo), "f"(hi));
    return r;
}
__device__ __forceinline__ void fma2(unsigned long long& d, unsigned long long a, unsigned long long b) {
    asm("fma.rn.f32x2 %0, %1, %2, %0;" : "+l"(d) : "l"(a), "l"(b));
}
__device__ __forceinline__ float2 unpack2(unsigned long long v) {
    float2 f;
    asm("mov.b64 {%0, %1}, %2;" : "=f"(f.x), "=f"(f.y) : "l"(v));
    return f;
}

// ---------------- RMSNorm ----------------
__global__ __launch_bounds__(256) void rmsnorm_kernel(
    const float* __restrict__ x, const float* __restrict__ w, float* __restrict__ o)
{
    __shared__ float red[8];
    const size_t row = blockIdx.x;
    const float4* xr = (const float4*)(x + row * DD);
    float ss = 0.f;
    #pragma unroll 2
    for (int i = threadIdx.x; i < DD / 4; i += 256) {
        float4 v = xr[i];
        ss += v.x * v.x + v.y * v.y + v.z * v.z + v.w * v.w;
    }
    #pragma unroll
    for (int off = 16; off; off >>= 1) ss += __shfl_xor_sync(0xffffffffu, ss, off);
    if ((threadIdx.x & 31) == 0) red[threadIdx.x >> 5] = ss;
    __syncthreads();
    float tot = red[0] + red[1] + red[2] + red[3] + red[4] + red[5] + red[6] + red[7];
    float rinv = rsqrtf(tot * (1.0f / DD) + 1e-6f);
    const float4* wr = (const float4*)w;
    float4* orow = (float4*)(o + row * DD);
    #pragma unroll 2
    for (int i = threadIdx.x; i < DD / 4; i += 256) {
        float4 v = xr[i], wv = wr[i];
        orow[i] = make_float4(v.x * rinv * wv.x, v.y * rinv * wv.y,
                              v.z * rinv * wv.z, v.w * rinv * wv.w);
    }
}

// ---------------- SGEMM (NT): C[M,N] = A[M,K] * B[N,K]^T (+ addv) ----------------
// 128x128 block tile, BK=16, 256 threads, 8x8 per-thread microtile with fma.rn.f32x2.
// All dims are multiples of 128/16 in this problem -> no bounds checks.
__global__ __launch_bounds__(256, 2) void sgemm_nt(
    const float* __restrict__ A, const float* __restrict__ Bw,
    const float* __restrict__ addv, float* __restrict__ C,
    int M, int N, int K)
{
    constexpr int BM = 128, BN = 128, BK = 16;
    __shared__ float As[BK][BM];
    __shared__ float Bs[BK][BN];
    const int tid  = threadIdx.x;
    const int trow = (tid >> 4) << 3;   // 0..120
    const int tcol = (tid & 15) << 3;   // 0..120
    const float* Ab = A  + (size_t)blockIdx.y * BM * K;
    const float* Bb = Bw + (size_t)blockIdx.x * BN * K;

    unsigned long long acc[8][4];
    #pragma unroll
    for (int i = 0; i < 8; i++)
        #pragma unroll
        for (int j = 0; j < 4; j++) acc[i][j] = 0ull;   // bits of {0.f,0.f}

    const int lrow = tid >> 2;          // 0..63
    const int lc4  = (tid & 3) << 2;    // 0,4,8,12

    for (int kt = 0; kt < K; kt += BK) {
        #pragma unroll
        for (int rr = 0; rr < 2; rr++) {
            int r = lrow + rr * 64;
            float4 va = *(const float4*)(Ab + (size_t)r * K + kt + lc4);
            As[lc4 + 0][r] = va.x; As[lc4 + 1][r] = va.y;
            As[lc4 + 2][r] = va.z; As[lc4 + 3][r] = va.w;
            float4 vb = *(const float4*)(Bb + (size_t)r * K + kt + lc4);
            Bs[lc4 + 0][r] = vb.x; Bs[lc4 + 1][r] = vb.y;
            Bs[lc4 + 2][r] = vb.z; Bs[lc4 + 3][r] = vb.w;
        }
        __syncthreads();
        #pragma unroll
        for (int kk = 0; kk < BK; kk++) {
            float4 a0 = *(const float4*)&As[kk][trow];
            float4 a1 = *(const float4*)&As[kk][trow + 4];
            float4 b0 = *(const float4*)&Bs[kk][tcol];
            float4 b1 = *(const float4*)&Bs[kk][tcol + 4];
            unsigned long long bb[4] = { pack2(b0.x, b0.y), pack2(b0.z, b0.w),
                                         pack2(b1.x, b1.y), pack2(b1.z, b1.w) };
            float av[8] = {a0.x, a0.y, a0.z, a0.w, a1.x, a1.y, a1.z, a1.w};
            #pragma unroll
            for (int i = 0; i < 8; i++) {
                unsigned long long aa = pack2(av[i], av[i]);
                #pragma unroll
                for (int j = 0; j < 4; j++) fma2(acc[i][j], aa, bb[j]);
            }
        }
        __syncthreads();
    }

    #pragma unroll
    for (int i = 0; i < 8; i++) {
        size_t row = (size_t)blockIdx.y * BM + trow + i;
        size_t cb  = row * N + (size_t)blockIdx.x * BN + tcol;
        float o[8];
        #pragma unroll
        for (int j = 0; j < 4; j++) {
            float2 f = unpack2(acc[i][j]);
            o[2 * j] = f.x; o[2 * j + 1] = f.y;
        }
        if (addv) {
            float4 r0 = *(const float4*)(addv + cb);
            float4 r1 = *(const float4*)(addv + cb + 4);
            o[0] += r0.x; o[1] += r0.y; o[2] += r0.z; o[3] += r0.w;
            o[4] += r1.x; o[5] += r1.y; o[6] += r1.z; o[7] += r1.w;
        }
        *(float4*)(C + cb)     = make_float4(o[0], o[1], o[2], o[3]);
        *(float4*)(C + cb + 4) = make_float4(o[4], o[5], o[6], o[7]);
    }
}

// ---------------- RoPE (interleaved pairs, first HD/2 of cos/sin) ----------------
__global__ void rope_kernel(float* __restrict__ x, const float* __restrict__ cs,
                            const float* __restrict__ sn, int nh)
{
    int idx = blockIdx.x * blockDim.x + threadIdx.x;
    int total = TT * nh * (HD / 2);
    if (idx >= total) return;
    int i = idx & 63;
    int h = (idx >> 6) % nh;
    int t = idx / (64 * nh);
    float c = cs[(size_t)t * HD + i];
    float s = sn[(size_t)t * HD + i];
    float* p = x + ((size_t)t * nh + h) * HD + 2 * i;
    float xr = p[0], xi = p[1];
    p[0] = c * xr - s * xi;
    p[1] = s * xr + c * xi;
}

// ---------------- Flash attention (fp32, 64x64 tiles, online softmax) ----------------
#define KSTRIDE 132
#define FA_SMEM ((64*128 + 64*KSTRIDE + 64*KSTRIDE + 64*64) * 4)  // 116736 B

__global__ __launch_bounds__(256, 1) void flash_kernel(
    const float* __restrict__ Q, const float* __restrict__ K,
    const float* __restrict__ V, const float* __restrict__ mask,
    float* __restrict__ O)
{
    extern __shared__ float sm[];
    float* sQ = sm;                       // 64 x 128
    float* sK = sQ + 64 * 128;            // 64 x 132
    float* sV = sK + 64 * KSTRIDE;        // 64 x 132
    float* sP = sV + 64 * KSTRIDE;        // 64 x 64

    const int qb = blockIdx.x, h = blockIdx.y, b = blockIdx.z;
    const int kvh = h >> 2;               // repeat_interleave: kv head = h / (H/KVH)
    const int tid = threadIdx.x, warp = tid >> 5, lane = tid & 31;
    const int r0 = warp * 8;
    const int d0 = lane * 4;
    const float scale = 0.08838834764831845f;   // HD^-0.5

    // load Q tile
    for (int idx = tid; idx < 64 * 32; idx += 256) {
        int r = idx >> 5, c4 = (idx & 31) << 2;
        *(float4*)(sQ + r * 128 + c4) =
            *(const float4*)(Q + ((size_t)(b * SS + qb * 64 + r) * HH + h) * HD + c4);
    }

    float m_i[8], l_i[8], accO[8][4];
    #pragma unroll
    for (int i = 0; i < 8; i++) {
        m_i[i] = -1e30f; l_i[i] = 0.f;
        accO[i][0] = accO[i][1] = accO[i][2] = accO[i][3] = 0.f;
    }

    for (int jb = 0; jb <= qb; jb++) {            // causal tile skip
        for (int idx = tid; idx < 64 * 32; idx += 256) {
            int c = idx >> 5, c4 = (idx & 31) << 2;
            size_t gk = ((size_t)(b * SS + jb * 64 + c) * KVH + kvh) * HD + c4;
            *(float4*)(sK + c * KSTRIDE + c4) = *(const float4*)(K + gk);
            *(float4*)(sV + c * KSTRIDE + c4) = *(const float4*)(V + gk);
        }
        __syncthreads();

        // S = Q K^T : per lane rows r0..r0+7, cols lane*2, lane*2+1
        float s0[8], s1[8];
        #pragma unroll
        for (int i = 0; i < 8; i++) { s0[i] = 0.f; s1[i] = 0.f; }
        #pragma unroll 4
        for (int k4 = 0; k4 < 32; k4++) {
            float4 kv0 = *(const float4*)(sK + (lane * 2)     * KSTRIDE + k4 * 4);
            float4 kv1 = *(const float4*)(sK + (lane * 2 + 1) * KSTRIDE + k4 * 4);
            #pragma unroll
            for (int i = 0; i < 8; i++) {
                float4 qv = *(const float4*)(sQ + (r0 + i) * 128 + k4 * 4);
                s0[i] += qv.x * kv0.x + qv.y * kv0.y + qv.z * kv0.z + qv.w * kv0.w;
                s1[i] += qv.x * kv1.x + qv.y * kv1.y + qv.z * kv1.z + qv.w * kv1.w;
            }
        }

        // additive mask + scale + online softmax
        const float* mrow = mask + ((size_t)b * SS + (size_t)qb * 64 + r0) * SS
                                 + (size_t)jb * 64 + lane * 2;
        float pscale[8];
        #pragma unroll
        for (int i = 0; i < 8; i++) {
            float2 mv = *(const float2*)(mrow + (size_t)i * SS);
            float v0 = s0[i] * scale + mv.x;
            float v1 = s1[i] * scale + mv.y;
            float mx = fmaxf(v0, v1);
            #pragma unroll
            for (int off = 16; off; off >>= 1)
                mx = fmaxf(mx, __shfl_xor_sync(0xffffffffu, mx, off));
            float mnew = fmaxf(m_i[i], mx);
            float p0 = __expf(v0 - mnew);
            float p1 = __expf(v1 - mnew);
            float rs = p0 + p1;
            #pragma unroll
            for (int off = 16; off; off >>= 1)
                rs += __shfl_xor_sync(0xffffffffu, rs, off);
            float sc = __expf(m_i[i] - mnew);
            l_i[i] = l_i[i] * sc + rs;
            m_i[i] = mnew;
            pscale[i] = sc;
            *(float2*)(sP + (r0 + i) * 64 + lane * 2) = make_float2(p0, p1);
        }
        __syncwarp();   // sP rows r0..r0+7 written/read by this warp only

        #pragma unroll
        for (int i = 0; i < 8; i++) {
            accO[i][0] *= pscale[i]; accO[i][1] *= pscale[i];
            accO[i][2] *= pscale[i]; accO[i][3] *= pscale[i];
        }

        // O += P V : per lane d-cols d0..d0+3
        #pragma unroll 2
        for (int c4 = 0; c4 < 16; c4++) {
            float4 v0 = *(const float4*)(sV + (c4 * 4 + 0) * KSTRIDE + d0);
            float4 v1 = *(const float4*)(sV + (c4 * 4 + 1) * KSTRIDE + d0);
            float4 v2 = *(const float4*)(sV + (c4 * 4 + 2) * KSTRIDE + d0);
            float4 v3 = *(const float4*)(sV + (c4 * 4 + 3) * KSTRIDE + d0);
            #pragma unroll
            for (int i = 0; i < 8; i++) {
                float4 p = *(const float4*)(sP + (r0 + i) * 64 + c4 * 4);
                accO[i][0] += p.x * v0.x + p.y * v1.x + p.z * v2.x + p.w * v3.x;
                accO[i][1] += p.x * v0.y + p.y * v1.y + p.z * v2.y + p.w * v3.y;
                accO[i][2] += p.x * v0.z + p.y * v1.z + p.z * v2.z + p.w * v3.z;
                accO[i][3] += p.x * v0.w + p.y * v1.w + p.z * v2.w + p.w * v3.w;
            }
        }
        __syncthreads();   // before next tile overwrites sK/sV
    }

    #pragma unroll
    for (int i = 0; i < 8; i++) {
        float inv = 1.0f / l_i[i];
        float4 o = make_float4(accO[i][0] * inv, accO[i][1] * inv,
                               accO[i][2] * inv, accO[i][3] * inv);
        *(float4*)(O + ((size_t)(b * SS + qb * 64 + r0 + i) * HH + h) * HD + d0) = o;
    }
}

// ---------------- silu(gate) * up (in-place into gate) ----------------
__global__ void silu_mul_kernel(float* __restrict__ g, const float* __restrict__ u, int n4)
{
    int idx = blockIdx.x * blockDim.x + threadIdx.x;
    if (idx >= n4) return;
    float4 gv = ((float4*)g)[idx];
    float4 uv = ((const float4*)u)[idx];
    gv.x = uv.x * gv.x / (1.f + __expf(-gv.x));
    gv.y = uv.y * gv.y / (1.f + __expf(-gv.y));
    gv.z = uv.z * gv.z / (1.f + __expf(-gv.z));
    gv.w = uv.w * gv.w / (1.f + __expf(-gv.w));
    ((float4*)g)[idx] = gv;
}

// ---------------- launch ----------------
extern "C" void kernel_launch(void* const* d_in, const int* in_sizes, int n_in,
                              void* d_out, int out_size)
{
    const float* hs   = (const float*)d_in[0];
    const float* cosp = (const float*)d_in[1];
    const float* sinp = (const float*)d_in[2];
    const float* mask = (const float*)d_in[3];
    const float* wq   = (const float*)d_in[4];
    const float* wk   = (const float*)d_in[5];
    const float* wv   = (const float*)d_in[6];
    const float* wo   = (const float*)d_in[7];
    const float* wg   = (const float*)d_in[8];
    const float* wu   = (const float*)d_in[9];
    const float* wd   = (const float*)d_in[10];
    const float* ln1  = (const float*)d_in[11];
    const float* ln2  = (const float*)d_in[12];
    float* out = (float*)d_out;

    float* base = nullptr;
    cudaGetSymbolAddress((void**)&base, g_scratch);
    float* xn   = base + OFF_XN;
    float* q    = base + OFF_Q;
    float* k    = base + OFF_K;
    float* v    = base + OFF_V;
    float* attn = base + OFF_ATTN;
    float* h2   = base + OFF_H2;
    float* xn2  = base + OFF_XN2;
    float* gate = base + OFF_GATE;
    float* up   = base + OFF_UP;

    // 1) pre-attn RMSNorm
    rmsnorm_kernel<<<TT, 256>>>(hs, ln1, xn);
    // 2) Q/K/V projections (NT GEMMs)
    sgemm_nt<<<dim3(16, 32), 256>>>(xn, wq, nullptr, q, TT, HH * HD, DD);
    sgemm_nt<<<dim3(4, 32),  256>>>(xn, wk, nullptr, k, TT, KVH * HD, DD);
    sgemm_nt<<<dim3(4, 32),  256>>>(xn, wv, nullptr, v, TT, KVH * HD, DD);
    // 3) RoPE
    rope_kernel<<<(TT * HH * 64) / 256, 256>>>(q, cosp, sinp, HH);
    rope_kernel<<<(TT * KVH * 64) / 256, 256>>>(k, cosp, sinp, KVH);
    // 4) attention
    cudaFuncSetAttribute((const void*)flash_kernel,
                         cudaFuncAttributeMaxDynamicSharedMemorySize, FA_SMEM);
    flash_kernel<<<dim3(SS / 64, HH, BB), 256, FA_SMEM>>>(q, k, v, mask, attn);
    // 5) output projection + residual
    sgemm_nt<<<dim3(16, 32), 256>>>(attn, wo, hs, h2, TT, DD, HH * HD);
    // 6) pre-MLP RMSNorm
    rmsnorm_kernel<<<TT, 256>>>(h2, ln2, xn2);
    // 7) MLP
    sgemm_nt<<<dim3(64, 32), 256>>>(xn2, wg, nullptr, gate, TT, II, DD);
    sgemm_nt<<<dim3(64, 32), 256>>>(xn2, wu, nullptr, up,   TT, II, DD);
    silu_mul_kernel<<<(TT * (II / 4)) / 256, 256>>>(gate, up, TT * (II / 4));
    // 8) down projection + residual -> output
    sgemm_nt<<<dim3(16, 32), 256>>>(gate, wd, h2, out, TT, DD, II);
}

// round 17
// speedup vs baseline: 2.1926x; 2.1926x over previous
#include <cuda_runtime.h>
#include <cuda_bf16.h>
#include <cstdint>

#define BB 2
#define SS 2048
#define DD 2048
#define HH 16
#define KVH 4
#define HD 128
#define II 8192
#define TT (BB*SS)   // 4096 tokens

// ---------------- scratch (static device memory; no allocations) ----------------
#define OFF_XN   ((size_t)0)
#define OFF_Q    ((size_t)8388608)
#define OFF_K    ((size_t)16777216)
#define OFF_V    ((size_t)18874368)
#define OFF_ATTN ((size_t)20971520)
#define OFF_H2   ((size_t)29360128)
#define OFF_XN2  ((size_t)37748736)
#define OFF_GATE ((size_t)46137344)
#define OFF_UP   ((size_t)79691776)
#define SCRATCH_FLOATS ((size_t)113246208)
__device__ float g_scratch[SCRATCH_FLOATS];

// ================= helpers =================
__device__ __forceinline__ uint32_t smem_u32(const void* p) {
    uint32_t a;
    asm("{ .reg .u64 t; cvta.to.shared.u64 t, %1; cvt.u32.u64 %0, t; }" : "=r"(a) : "l"(p));
    return a;
}

// Split fp32 -> (bf16 hi rounded, bf16 lo residual); store 4 of each (8B STS x2)
__device__ __forceinline__ void cvt_store(uint32_t hi_addr, uint32_t lo_addr, float4 v) {
    uint32_t u0 = __float_as_uint(v.x) + 0x8000u;
    uint32_t u1 = __float_as_uint(v.y) + 0x8000u;
    uint32_t u2 = __float_as_uint(v.z) + 0x8000u;
    uint32_t u3 = __float_as_uint(v.w) + 0x8000u;
    uint32_t h01 = __byte_perm(u0, u1, 0x7632);
    uint32_t h23 = __byte_perm(u2, u3, 0x7632);
    float l0 = v.x - __uint_as_float(u0 & 0xFFFF0000u);
    float l1 = v.y - __uint_as_float(u1 & 0xFFFF0000u);
    float l2 = v.z - __uint_as_float(u2 & 0xFFFF0000u);
    float l3 = v.w - __uint_as_float(u3 & 0xFFFF0000u);
    uint32_t lo01, lo23;
    asm("cvt.rn.bf16x2.f32 %0, %1, %2;" : "=r"(lo01) : "f"(l1), "f"(l0));
    asm("cvt.rn.bf16x2.f32 %0, %1, %2;" : "=r"(lo23) : "f"(l3), "f"(l2));
    asm volatile("st.shared.v2.b32 [%0], {%1,%2};" :: "r"(hi_addr), "r"(h01), "r"(h23) : "memory");
    asm volatile("st.shared.v2.b32 [%0], {%1,%2};" :: "r"(lo_addr), "r"(lo01), "r"(lo23) : "memory");
}

__device__ __forceinline__ void ldmx4(uint32_t* r, uint32_t addr) {
    asm volatile("ldmatrix.sync.aligned.m8n8.x4.shared.b16 {%0,%1,%2,%3}, [%4];"
                 : "=r"(r[0]), "=r"(r[1]), "=r"(r[2]), "=r"(r[3]) : "r"(addr));
}

__device__ __forceinline__ void mma_bf16(float* c, const uint32_t* a, uint32_t b0, uint32_t b1) {
    asm volatile(
        "mma.sync.aligned.m16n8k16.row.col.f32.bf16.bf16.f32 "
        "{%0,%1,%2,%3}, {%4,%5,%6,%7}, {%8,%9}, {%0,%1,%2,%3};"
        : "+f"(c[0]), "+f"(c[1]), "+f"(c[2]), "+f"(c[3])
        : "r"(a[0]), "r"(a[1]), "r"(a[2]), "r"(a[3]), "r"(b0), "r"(b1));
}

// ================= HMMA split-bf16 GEMM (NT): C = A[M,K] * B[N,K]^T (+addv) =========
// 128x128 CTA tile, BK=32, planes Ah/Al/Bh/Bl (80B row stride), double-buffered.
#define GPLANE 10240u         // 128 rows * 80 B
#define GSTAGE (4u*GPLANE)    // 40960 B
#define GSMEM  (2*40960 + 128)

__global__ __launch_bounds__(256, 1) void gemm_hmma(
    const float* __restrict__ A, const float* __restrict__ Bw,
    const float* __restrict__ addv, float* __restrict__ C,
    int M, int N, int K)
{
    extern __shared__ char dsm[];
    const uint32_t base = (smem_u32(dsm) + 127u) & ~127u;
    const int tid = threadIdx.x;
    const int warp = tid >> 5, lane = tid & 31;
    const int wm = warp & 3;        // 4 warps along M (32 rows each)
    const int wn = warp >> 2;       // 2 warps along N (64 cols each)

    // global staging: thread handles rows lrow..lrow+3, k-chunk lcol..lcol+3
    const int lrow = (tid >> 3) << 2;
    const int lcol = (tid & 7) << 2;
    const float* Ab = A  + (size_t)blockIdx.y * 128 * K;
    const float* Bb = Bw + (size_t)blockIdx.x * 128 * K;

    float acc[2][8][4];
    #pragma unroll
    for (int i = 0; i < 2; i++)
        #pragma unroll
        for (int j = 0; j < 8; j++)
            acc[i][j][0] = acc[i][j][1] = acc[i][j][2] = acc[i][j][3] = 0.f;

    // ldmatrix base offsets (16B-aligned: 80 = 5*16)
    const uint32_t aoff = (uint32_t)(wm * 32 + (lane & 15)) * 80u + ((uint32_t)(lane >> 4) << 4);
    const uint32_t boff = (uint32_t)(wn * 64 + (lane & 15)) * 80u + ((uint32_t)(lane >> 4) << 4);

    const int niter = K >> 5;
    float4 pa[4], pb[4];

    // prologue: load + stage 0
    #pragma unroll
    for (int r = 0; r < 4; r++) {
        pa[r] = *(const float4*)(Ab + (size_t)(lrow + r) * K + lcol);
        pb[r] = *(const float4*)(Bb + (size_t)(lrow + r) * K + lcol);
    }
    {
        uint32_t sb = base;
        #pragma unroll
        for (int r = 0; r < 4; r++) {
            uint32_t off = (uint32_t)(lrow + r) * 80u + ((uint32_t)lcol << 1);
            cvt_store(sb + off,              sb + GPLANE + off,      pa[r]);
            cvt_store(sb + 2u*GPLANE + off,  sb + 3u*GPLANE + off,   pb[r]);
        }
    }
    __syncthreads();

    for (int kt = 0; kt < niter; ++kt) {
        if (kt + 1 < niter) {
            const int kb = (kt + 1) << 5;
            #pragma unroll
            for (int r = 0; r < 4; r++) {
                pa[r] = *(const float4*)(Ab + (size_t)(lrow + r) * K + kb + lcol);
                pb[r] = *(const float4*)(Bb + (size_t)(lrow + r) * K + kb + lcol);
            }
        }

        const uint32_t sb = base + (uint32_t)(kt & 1) * GSTAGE;
        #pragma unroll
        for (int ks = 0; ks < 2; ++ks) {
            const uint32_t kb = (uint32_t)ks * 32u;
            uint32_t ah[2][4], al[2][4], bh[4][4], bl[4][4];
            #pragma unroll
            for (int i = 0; i < 2; i++) {
                ldmx4(ah[i], sb              + aoff + (uint32_t)i * 1280u + kb);
                ldmx4(al[i], sb + GPLANE     + aoff + (uint32_t)i * 1280u + kb);
            }
            #pragma unroll
            for (int jj = 0; jj < 4; jj++) {
                ldmx4(bh[jj], sb + 2u*GPLANE + boff + (uint32_t)jj * 1280u + kb);
                ldmx4(bl[jj], sb + 3u*GPLANE + boff + (uint32_t)jj * 1280u + kb);
            }
            #pragma unroll
            for (int i = 0; i < 2; i++)
                #pragma unroll
                for (int j = 0; j < 8; j++) {
                    const int jj = j >> 1, o = j & 1;
                    mma_bf16(acc[i][j], ah[i], bh[jj][o], bh[jj][2 + o]);   // Ah*Bh
                    mma_bf16(acc[i][j], ah[i], bl[jj][o], bl[jj][2 + o]);   // Ah*Bl
                    mma_bf16(acc[i][j], al[i], bh[jj][o], bh[jj][2 + o]);   // Al*Bh
                }
        }

        if (kt + 1 < niter) {
            const uint32_t so = base + (uint32_t)((kt + 1) & 1) * GSTAGE;
            #pragma unroll
            for (int r = 0; r < 4; r++) {
                uint32_t off = (uint32_t)(lrow + r) * 80u + ((uint32_t)lcol << 1);
                cvt_store(so + off,              so + GPLANE + off,     pa[r]);
                cvt_store(so + 2u*GPLANE + off,  so + 3u*GPLANE + off,  pb[r]);
            }
            __syncthreads();
        }
    }

    // epilogue: fragment layout rows gid/gid+8, cols 2*(lane&3)+{0,1}
    #pragma unroll
    for (int i = 0; i < 2; i++) {
        const int row0 = (int)blockIdx.y * 128 + wm * 32 + i * 16 + (lane >> 2);
        #pragma unroll
        for (int j = 0; j < 8; j++) {
            const int col = (int)blockIdx.x * 128 + wn * 64 + j * 8 + ((lane & 3) << 1);
            size_t p0 = (size_t)row0 * N + col;
            size_t p1 = (size_t)(row0 + 8) * N + col;
            float2 v0 = make_float2(acc[i][j][0], acc[i][j][1]);
            float2 v1 = make_float2(acc[i][j][2], acc[i][j][3]);
            if (addv) {
                float2 r0 = *(const float2*)(addv + p0);
                float2 r1 = *(const float2*)(addv + p1);
                v0.x += r0.x; v0.y += r0.y;
                v1.x += r1.x; v1.y += r1.y;
            }
            *(float2*)(C + p0) = v0;
            *(float2*)(C + p1) = v1;
        }
    }
}

// ---------------- RMSNorm ----------------
__global__ __launch_bounds__(256) void rmsnorm_kernel(
    const float* __restrict__ x, const float* __restrict__ w, float* __restrict__ o)
{
    __shared__ float red[8];
    const size_t row = blockIdx.x;
    const float4* xr = (const float4*)(x + row * DD);
    float ss = 0.f;
    #pragma unroll 2
    for (int i = threadIdx.x; i < DD / 4; i += 256) {
        float4 v = xr[i];
        ss += v.x * v.x + v.y * v.y + v.z * v.z + v.w * v.w;
    }
    #pragma unroll
    for (int off = 16; off; off >>= 1) ss += __shfl_xor_sync(0xffffffffu, ss, off);
    if ((threadIdx.x & 31) == 0) red[threadIdx.x >> 5] = ss;
    __syncthreads();
    float tot = red[0] + red[1] + red[2] + red[3] + red[4] + red[5] + red[6] + red[7];
    float rinv = rsqrtf(tot * (1.0f / DD) + 1e-6f);
    const float4* wr = (const float4*)w;
    float4* orow = (float4*)(o + row * DD);
    #pragma unroll 2
    for (int i = threadIdx.x; i < DD / 4; i += 256) {
        float4 v = xr[i], wv = wr[i];
        orow[i] = make_float4(v.x * rinv * wv.x, v.y * rinv * wv.y,
                              v.z * rinv * wv.z, v.w * rinv * wv.w);
    }
}

// ---------------- RoPE ----------------
__global__ void rope_kernel(float* __restrict__ x, const float* __restrict__ cs,
                            const float* __restrict__ sn, int nh)
{
    int idx = blockIdx.x * blockDim.x + threadIdx.x;
    int total = TT * nh * (HD / 2);
    if (idx >= total) return;
    int i = idx & 63;
    int h = (idx >> 6) % nh;
    int t = idx / (64 * nh);
    float c = cs[(size_t)t * HD + i];
    float s = sn[(size_t)t * HD + i];
    float* p = x + ((size_t)t * nh + h) * HD + 2 * i;
    float xr = p[0], xi = p[1];
    p[0] = c * xr - s * xi;
    p[1] = s * xr + c * xi;
}

// ---------------- Flash attention (fp32, 64x64 tiles, online softmax) ----------------
#define KSTRIDE 132
#define FA_SMEM ((64*128 + 64*KSTRIDE + 64*KSTRIDE + 64*64) * 4)  // 116736 B

__global__ __launch_bounds__(256, 1) void flash_kernel(
    const float* __restrict__ Q, const float* __restrict__ K,
    const float* __restrict__ V, const float* __restrict__ mask,
    float* __restrict__ O)
{
    extern __shared__ float sm[];
    float* sQ = sm;
    float* sK = sQ + 64 * 128;
    float* sV = sK + 64 * KSTRIDE;
    float* sP = sV + 64 * KSTRIDE;

    const int qb = blockIdx.x, h = blockIdx.y, b = blockIdx.z;
    const int kvh = h >> 2;
    const int tid = threadIdx.x, warp = tid >> 5, lane = tid & 31;
    const int r0 = warp * 8;
    const int d0 = lane * 4;
    const float scale = 0.08838834764831845f;

    for (int idx = tid; idx < 64 * 32; idx += 256) {
        int r = idx >> 5, c4 = (idx & 31) << 2;
        *(float4*)(sQ + r * 128 + c4) =
            *(const float4*)(Q + ((size_t)(b * SS + qb * 64 + r) * HH + h) * HD + c4);
    }

    float m_i[8], l_i[8], accO[8][4];
    #pragma unroll
    for (int i = 0; i < 8; i++) {
        m_i[i] = -1e30f; l_i[i] = 0.f;
        accO[i][0] = accO[i][1] = accO[i][2] = accO[i][3] = 0.f;
    }

    for (int jb = 0; jb <= qb; jb++) {
        for (int idx = tid; idx < 64 * 32; idx += 256) {
            int c = idx >> 5, c4 = (idx & 31) << 2;
            size_t gk = ((size_t)(b * SS + jb * 64 + c) * KVH + kvh) * HD + c4;
            *(float4*)(sK + c * KSTRIDE + c4) = *(const float4*)(K + gk);
            *(float4*)(sV + c * KSTRIDE + c4) = *(const float4*)(V + gk);
        }
        __syncthreads();

        float s0[8], s1[8];
        #pragma unroll
        for (int i = 0; i < 8; i++) { s0[i] = 0.f; s1[i] = 0.f; }
        #pragma unroll 4
        for (int k4 = 0; k4 < 32; k4++) {
            float4 kv0 = *(const float4*)(sK + (lane * 2)     * KSTRIDE + k4 * 4);
            float4 kv1 = *(const float4*)(sK + (lane * 2 + 1) * KSTRIDE + k4 * 4);
            #pragma unroll
            for (int i = 0; i < 8; i++) {
                float4 qv = *(const float4*)(sQ + (r0 + i) * 128 + k4 * 4);
                s0[i] += qv.x * kv0.x + qv.y * kv0.y + qv.z * kv0.z + qv.w * kv0.w;
                s1[i] += qv.x * kv1.x + qv.y * kv1.y + qv.z * kv1.z + qv.w * kv1.w;
            }
        }

        const float* mrow = mask + ((size_t)b * SS + (size_t)qb * 64 + r0) * SS
                                 + (size_t)jb * 64 + lane * 2;
        float pscale[8];
        #pragma unroll
        for (int i = 0; i < 8; i++) {
            float2 mv = *(const float2*)(mrow + (size_t)i * SS);
            float v0 = s0[i] * scale + mv.x;
            float v1 = s1[i] * scale + mv.y;
            float mx = fmaxf(v0, v1);
            #pragma unroll
            for (int off = 16; off; off >>= 1)
                mx = fmaxf(mx, __shfl_xor_sync(0xffffffffu, mx, off));
            float mnew = fmaxf(m_i[i], mx);
            float p0 = __expf(v0 - mnew);
            float p1 = __expf(v1 - mnew);
            float rs = p0 + p1;
            #pragma unroll
            for (int off = 16; off; off >>= 1)
                rs += __shfl_xor_sync(0xffffffffu, rs, off);
            float sc = __expf(m_i[i] - mnew);
            l_i[i] = l_i[i] * sc + rs;
            m_i[i] = mnew;
            pscale[i] = sc;
            *(float2*)(sP + (r0 + i) * 64 + lane * 2) = make_float2(p0, p1);
        }
        __syncwarp();

        #pragma unroll
        for (int i = 0; i < 8; i++) {
            accO[i][0] *= pscale[i]; accO[i][1] *= pscale[i];
            accO[i][2] *= pscale[i]; accO[i][3] *= pscale[i];
        }

        #pragma unroll 2
        for (int c4 = 0; c4 < 16; c4++) {
            float4 v0 = *(const float4*)(sV + (c4 * 4 + 0) * KSTRIDE + d0);
            float4 v1 = *(const float4*)(sV + (c4 * 4 + 1) * KSTRIDE + d0);
            float4 v2 = *(const float4*)(sV + (c4 * 4 + 2) * KSTRIDE + d0);
            float4 v3 = *(const float4*)(sV + (c4 * 4 + 3) * KSTRIDE + d0);
            #pragma unroll
            for (int i = 0; i < 8; i++) {
                float4 p = *(const float4*)(sP + (r0 + i) * 64 + c4 * 4);
                accO[i][0] += p.x * v0.x + p.y * v1.x + p.z * v2.x + p.w * v3.x;
                accO[i][1] += p.x * v0.y + p.y * v1.y + p.z * v2.y + p.w * v3.y;
                accO[i][2] += p.x * v0.z + p.y * v1.z + p.z * v2.z + p.w * v3.z;
                accO[i][3] += p.x * v0.w + p.y * v1.w + p.z * v2.w + p.w * v3.w;
            }
        }
        __syncthreads();
    }

    #pragma unroll
    for (int i = 0; i < 8; i++) {
        float inv = 1.0f / l_i[i];
        float4 o = make_float4(accO[i][0] * inv, accO[i][1] * inv,
                               accO[i][2] * inv, accO[i][3] * inv);
        *(float4*)(O + ((size_t)(b * SS + qb * 64 + r0 + i) * HH + h) * HD + d0) = o;
    }
}

// ---------------- silu(gate) * up ----------------
__global__ void silu_mul_kernel(float* __restrict__ g, const float* __restrict__ u, int n4)
{
    int idx = blockIdx.x * blockDim.x + threadIdx.x;
    if (idx >= n4) return;
    float4 gv = ((float4*)g)[idx];
    float4 uv = ((const float4*)u)[idx];
    gv.x = uv.x * gv.x / (1.f + __expf(-gv.x));
    gv.y = uv.y * gv.y / (1.f + __expf(-gv.y));
    gv.z = uv.z * gv.z / (1.f + __expf(-gv.z));
    gv.w = uv.w * gv.w / (1.f + __expf(-gv.w));
    ((float4*)g)[idx] = gv;
}

// ---------------- launch ----------------
extern "C" void kernel_launch(void* const* d_in, const int* in_sizes, int n_in,
                              void* d_out, int out_size)
{
    const float* hs   = (const float*)d_in[0];
    const float* cosp = (const float*)d_in[1];
    const float* sinp = (const float*)d_in[2];
    const float* mask = (const float*)d_in[3];
    const float* wq   = (const float*)d_in[4];
    const float* wk   = (const float*)d_in[5];
    const float* wv   = (const float*)d_in[6];
    const float* wo   = (const float*)d_in[7];
    const float* wg   = (const float*)d_in[8];
    const float* wu   = (const float*)d_in[9];
    const float* wd   = (const float*)d_in[10];
    const float* ln1  = (const float*)d_in[11];
    const float* ln2  = (const float*)d_in[12];
    float* out = (float*)d_out;

    float* base = nullptr;
    cudaGetSymbolAddress((void**)&base, g_scratch);
    float* xn   = base + OFF_XN;
    float* q    = base + OFF_Q;
    float* k    = base + OFF_K;
    float* v    = base + OFF_V;
    float* attn = base + OFF_ATTN;
    float* h2   = base + OFF_H2;
    float* xn2  = base + OFF_XN2;
    float* gate = base + OFF_GATE;
    float* up   = base + OFF_UP;

    cudaFuncSetAttribute((const void*)gemm_hmma,
                         cudaFuncAttributeMaxDynamicSharedMemorySize, GSMEM);
    cudaFuncSetAttribute((const void*)flash_kernel,
                         cudaFuncAttributeMaxDynamicSharedMemorySize, FA_SMEM);

    // 1) pre-attn RMSNorm
    rmsnorm_kernel<<<TT, 256>>>(hs, ln1, xn);
    // 2) Q/K/V projections (HMMA split-bf16 GEMMs)
    gemm_hmma<<<dim3(16, 32), 256, GSMEM>>>(xn, wq, nullptr, q, TT, HH * HD, DD);
    gemm_hmma<<<dim3(4, 32),  256, GSMEM>>>(xn, wk, nullptr, k, TT, KVH * HD, DD);
    gemm_hmma<<<dim3(4, 32),  256, GSMEM>>>(xn, wv, nullptr, v, TT, KVH * HD, DD);
    // 3) RoPE
    rope_kernel<<<(TT * HH * 64) / 256, 256>>>(q, cosp, sinp, HH);
    rope_kernel<<<(TT * KVH * 64) / 256, 256>>>(k, cosp, sinp, KVH);
    // 4) attention
    flash_kernel<<<dim3(SS / 64, HH, BB), 256, FA_SMEM>>>(q, k, v, mask, attn);
    // 5) output projection + residual
    gemm_hmma<<<dim3(16, 32), 256, GSMEM>>>(attn, wo, hs, h2, TT, DD, HH * HD);
    // 6) pre-MLP RMSNorm
    rmsnorm_kernel<<<TT, 256>>>(h2, ln2, xn2);
    // 7) MLP
    gemm_hmma<<<dim3(64, 32), 256, GSMEM>>>(xn2, wg, nullptr, gate, TT, II, DD);
    gemm_hmma<<<dim3(64, 32), 256, GSMEM>>>(xn2, wu, nullptr, up,   TT, II, DD);
    silu_mul_kernel<<<(TT * (II / 4)) / 256, 256>>>(gate, up, TT * (II / 4));
    // 8) down projection + residual -> output
    gemm_hmma<<<dim3(16, 32), 256, GSMEM>>>(gate, wd, h2, out, TT, DD, II);
}